// round 6
// baseline (speedup 1.0000x reference)
#include <cuda_runtime.h>
#include <cstdint>
#include <cstddef>

// Problem dims
#define Bn 64
#define Tn 2048
#define Fn 256
#define Hn 512
#define On 128

// Partition (R3 geometry): 8 groups x 8 batches, 16 slices x 32 cols = 128 CTAs
#define NG 8
#define GB 8
#define NS 16
#define SC 32
#define NKG 16
#define KC 32
#define NCOMP 512
#define NTHR 544            // 16 compute warps + 1 comm warp
#define WSTRIDE 516
#define HB (GB * Hn * 4)    // 16384 bytes per hidden-state exchange

// ---------------- static device workspaces -------------------------------------
__device__ __align__(128) float g_xp[(size_t)Bn * Tn * Hn];   // 256 MB input proj
__device__ __align__(128) float g_h0buf[2][NG][GB * Hn];
__device__ __align__(128) float g_h1buf[2][NG][GB * Hn];
__device__ __align__(128) float g_hT[Bn * Hn];
__device__ unsigned g_flags0[NG][NS];
__device__ unsigned g_flags1[NG][NS];

typedef unsigned long long u64t;

// ---------------- packed fp32x2 + sync helpers ----------------------------------
__device__ __forceinline__ u64t fma2(u64t a, u64t b, u64t c) {
    u64t d;
    asm("fma.rn.f32x2 %0, %1, %2, %3;" : "=l"(d) : "l"(a), "l"(b), "l"(c));
    return d;
}
__device__ __forceinline__ u64t pk2(float lo, float hi) {
    u64t r;
    asm("mov.b64 %0, {%1, %2};" : "=l"(r) : "f"(lo), "f"(hi));
    return r;
}
__device__ __forceinline__ float2 upk(u64t v) {
    float2 f;
    asm("mov.b64 {%0, %1}, %2;" : "=f"(f.x), "=f"(f.y) : "l"(v));
    return f;
}
__device__ __forceinline__ unsigned ld_acq(const unsigned* p) {
    unsigned v;
    asm volatile("ld.global.acquire.gpu.u32 %0, [%1];" : "=r"(v) : "l"(p));
    return v;
}
__device__ __forceinline__ void st_rel(unsigned* p, unsigned v) {
    asm volatile("st.global.release.gpu.u32 [%0], %1;" :: "l"(p), "r"(v) : "memory");
}
__device__ __forceinline__ unsigned smem_u32(const void* p) {
    unsigned a;
    asm("{ .reg .u64 t; cvta.to.shared.u64 t, %1; cvt.u32.u64 %0, t; }" : "=r"(a) : "l"(p));
    return a;
}
__device__ __forceinline__ void mbar_init(unsigned m, unsigned cnt) {
    asm volatile("mbarrier.init.shared.b64 [%0], %1;" :: "r"(m), "r"(cnt) : "memory");
}
__device__ __forceinline__ void mbar_expect_tx(unsigned m, unsigned bytes) {
    asm volatile("mbarrier.arrive.expect_tx.shared.b64 _, [%0], %1;" :: "r"(m), "r"(bytes) : "memory");
}
__device__ __forceinline__ void bulk_g2s(unsigned dst, const void* src, unsigned bytes, unsigned m) {
    asm volatile("cp.async.bulk.shared::cluster.global.mbarrier::complete_tx::bytes [%0], [%1], %2, [%3];"
                 :: "r"(dst), "l"(src), "r"(bytes), "r"(m) : "memory");
}
__device__ __forceinline__ void mbar_wait(unsigned m, int phase) {
    asm volatile(
        "{\n\t.reg .pred P;\n"
        "WL%=:\n\t"
        "mbarrier.try_wait.parity.acquire.cta.shared::cta.b64 P, [%0], %1, 0x989680;\n\t"
        "@P bra WD%=;\n\t"
        "bra WL%=;\n"
        "WD%=:\n\t}"
        :: "r"(m), "r"((unsigned)phase) : "memory");
}
__device__ __forceinline__ void bar_sync(int id, int cnt) {
    asm volatile("bar.sync %0, %1;" :: "r"(id), "r"(cnt) : "memory");
}
__device__ __forceinline__ void bar_arrive(int id, int cnt) {
    asm volatile("bar.arrive %0, %1;" :: "r"(id), "r"(cnt) : "memory");
}

// ---------------- GEMM1: g_xp[M,512] = x[M,256] * W_ih0[512,256]^T + b ----------
__global__ __launch_bounds__(256) void sgemm_xp(
    const float* __restrict__ A, const float* __restrict__ Wm,
    const float* __restrict__ b1, const float* __restrict__ b2)
{
    __shared__ float As[8][128];
    __shared__ float Ws[8][128];

    const int tid = threadIdx.x;
    if (blockIdx.x == 0 && blockIdx.y == 0 && tid < NG * NS) {
        ((unsigned*)g_flags0)[tid] = 0u;
        ((unsigned*)g_flags1)[tid] = 0u;
    }

    const int K = Fn;
    const int bm = blockIdx.x, bn = blockIdx.y;
    const int row = tid >> 1;
    const int kq = (tid & 1) * 4;
    const float* Ag = A + (size_t)(bm * 128 + row) * K + kq;
    const float* Wg = Wm + (size_t)(bn * 128 + row) * K + kq;
    const int tx = tid & 15, ty = tid >> 4;
    const int m0 = ty * 8, n0 = tx * 8;

    u64t acc[8][4];
#pragma unroll
    for (int i = 0; i < 8; i++)
#pragma unroll
        for (int j = 0; j < 4; j++) acc[i][j] = 0ull;

    float4 ap = *(const float4*)Ag;
    float4 wp = *(const float4*)Wg;
    const int nk = K >> 3;

    for (int kt = 0; kt < nk; kt++) {
        As[kq + 0][row] = ap.x; As[kq + 1][row] = ap.y;
        As[kq + 2][row] = ap.z; As[kq + 3][row] = ap.w;
        Ws[kq + 0][row] = wp.x; Ws[kq + 1][row] = wp.y;
        Ws[kq + 2][row] = wp.z; Ws[kq + 3][row] = wp.w;
        __syncthreads();
        if (kt + 1 < nk) {
            ap = *(const float4*)(Ag + (size_t)(kt + 1) * 8);
            wp = *(const float4*)(Wg + (size_t)(kt + 1) * 8);
        }
#pragma unroll
        for (int k = 0; k < 8; k++) {
            float4 a0 = *(const float4*)&As[k][m0];
            float4 a1 = *(const float4*)&As[k][m0 + 4];
            const u64t* bp = (const u64t*)&Ws[k][n0];
            u64t bv0 = bp[0], bv1 = bp[1], bv2 = bp[2], bv3 = bp[3];
            float av[8] = {a0.x, a0.y, a0.z, a0.w, a1.x, a1.y, a1.z, a1.w};
#pragma unroll
            for (int i = 0; i < 8; i++) {
                u64t ai = pk2(av[i], av[i]);
                acc[i][0] = fma2(ai, bv0, acc[i][0]);
                acc[i][1] = fma2(ai, bv1, acc[i][1]);
                acc[i][2] = fma2(ai, bv2, acc[i][2]);
                acc[i][3] = fma2(ai, bv3, acc[i][3]);
            }
        }
        __syncthreads();
    }

    const int gn = bn * 128 + n0;
    float bs[8];
#pragma unroll
    for (int j = 0; j < 8; j++) bs[j] = b1[gn + j] + b2[gn + j];
#pragma unroll
    for (int i = 0; i < 8; i++) {
        float* cp = g_xp + (size_t)(bm * 128 + m0 + i) * Hn + gn;
        float2 p0 = upk(acc[i][0]), p1 = upk(acc[i][1]);
        float2 p2 = upk(acc[i][2]), p3 = upk(acc[i][3]);
        *(float4*)cp       = make_float4(p0.x + bs[0], p0.y + bs[1], p1.x + bs[2], p1.y + bs[3]);
        *(float4*)(cp + 4) = make_float4(p2.x + bs[4], p2.y + bs[5], p3.x + bs[6], p3.y + bs[7]);
    }
}

// ---------------- fused two-layer recurrence: R3 geometry + comm warp -----------
// Step t: phase A computes h0_t (from h0_{t-1}); phase B computes h1_{t-1}
// (from h1_{t-2} and h0_{t-1}). All inputs were published in step t-1. The comm
// warp (warp 16) owns flag polls, TMA issue, and mbarrier waits; it releases
// SMEM buffers to the 16 compute warps via bar.arrive on named barriers 1 (h0)
// and 2 (h1). Compute warps execute only bar.sync — no polls, no try_waits.
__global__ __launch_bounds__(NTHR, 1) void fused_rnn(
    const float* __restrict__ Whh0, const float* __restrict__ Wih1,
    const float* __restrict__ Whh1,
    const float* __restrict__ bih1, const float* __restrict__ bhh1,
    const float* __restrict__ h00, const float* __restrict__ h01)
{
    extern __shared__ float sm[];
    float* wih1  = sm;                   // SC*WSTRIDE = 16512 floats
    float* shh0  = sm + SC * WSTRIDE;    // 2 x GB*Hn (parity)
    float* shh1  = shh0 + 2 * GB * Hn;   // 2 x GB*Hn
    float* part0 = shh1 + 2 * GB * Hn;   // NKG*256 = 4096
    float* part1 = part0 + NKG * 256;    // 4096
    __shared__ __align__(8) unsigned long long mbar[2];

    const int tid = threadIdx.x;
    const int slice = blockIdx.x & (NS - 1);
    const int group = blockIdx.x >> 4;
    const bool comm = (tid >= NCOMP);
    const int j = tid & 31;
    const int kg = (tid >> 5) & 15;
    const int kb = kg * KC;

    // compute warps: recurrence weight chunks in registers (32 floats/matrix)
    u64t w0[16], w1[16];
    if (!comm) {
        const int col = slice * SC + j;
        const ulonglong2* p0 = (const ulonglong2*)(Whh0 + (size_t)col * Hn + kb);
        const ulonglong2* p1 = (const ulonglong2*)(Whh1 + (size_t)col * Hn + kb);
#pragma unroll
        for (int i = 0; i < 8; i++) {
            ulonglong2 a = p0[i]; w0[2 * i] = a.x; w0[2 * i + 1] = a.y;
            ulonglong2 b = p1[i]; w1[2 * i] = b.x; w1[2 * i + 1] = b.y;
        }
    }
    // W_ih1 slice into padded SMEM (all threads help)
    for (int idx = tid; idx < SC * Hn; idx += NTHR) {
        int r = idx >> 9, k = idx & 511;
        wih1[r * WSTRIDE + k] = Wih1[(size_t)(slice * SC + r) * Hn + k];
    }
    // preload: shh0 parity0 = h00 (step 0); shh1 parity1 = h01 (step 1)
    for (int idx = tid; idx < GB * Hn; idx += NTHR) {
        shh0[idx] = h00[idx & 511];
        shh1[GB * Hn + idx] = h01[idx & 511];
    }

    const unsigned mb0 = smem_u32(&mbar[0]);
    const unsigned mb1 = smem_u32(&mbar[1]);
    const unsigned sh0a = smem_u32(shh0);
    const unsigned sh1a = smem_u32(shh1);
    if (tid == 0) {
        mbar_init(mb0, 1);
        mbar_init(mb1, 1);
        asm volatile("fence.proxy.async.shared::cta;" ::: "memory");
    }

    // reducer role (tid < 256): (batch rb, col rj)
    const int rb = tid >> 5, rj = tid & 31;
    const int rcol = slice * SC + rj;
    const float bias1 = bih1[rcol] + bhh1[rcol];
    const size_t xbase = ((size_t)(group * GB + rb) * Tn) * Hn + rcol;
    float xpv = (tid < 256) ? __ldg(g_xp + xbase) : 0.f;
    unsigned* f0g = &g_flags0[group][0];
    unsigned* f1g = &g_flags1[group][0];
    __syncthreads();

    if (comm) {
        // ---------------- communication warp ----------------
        const int lane = tid - NCOMP;
        int ph0 = 0, ph1 = 0;
#pragma unroll 1
        for (int t = 0; t <= Tn; t++) {
            const int cur = t & 1, nxt = cur ^ 1;
            // release shh0[cur] = h0_{t-1}
            if (t > 0) {
                if (lane == 0) mbar_wait(mb0, ph0);
                __syncwarp();
                ph0 ^= 1;
            }
            bar_arrive(1, NTHR);
            // release shh1[cur] = h1_{t-2}
            if (t >= 1) {
                if (t >= 2) {
                    if (lane == 0) mbar_wait(mb1, ph1);
                    __syncwarp();
                    ph1 ^= 1;
                }
                bar_arrive(2, NTHR);
            }
            if (t < Tn) {
                // TMA0: h0_t (published during phase A of step t) -> shh0[nxt]
                if (lane < NS) { while (ld_acq(&f0g[lane]) < (unsigned)(t + 1)) {} }
                __syncwarp();
                if (lane == 0) {
                    mbar_expect_tx(mb0, HB);
                    bulk_g2s(sh0a + nxt * HB, &g_h0buf[cur][group][0], HB, mb0);
                }
                // TMA1: h1_{t-1} (published during phase B of step t) -> shh1[nxt]
                if (t >= 1) {
                    if (lane < NS) { while (ld_acq(&f1g[lane]) < (unsigned)t) {} }
                    __syncwarp();
                    if (lane == 0) {
                        mbar_expect_tx(mb1, HB);
                        bulk_g2s(sh1a + nxt * HB, &g_h1buf[cur][group][0], HB, mb1);
                    }
                }
            }
        }
        return;
    }

    // ---------------- compute warps ----------------
    u64t acc[GB];
#pragma unroll 1
    for (int t = 0; t <= Tn; t++) {
        const int cur = t & 1;
        const float* h0c = shh0 + cur * (GB * Hn);
        const float* h1c = shh1 + cur * (GB * Hn);

        bar_sync(1, NTHR);   // shh0[cur] = h0_{t-1} ready

        if (t < Tn) {
            // ---- phase A: mv0 = W_hh0 . h0_{t-1}
#pragma unroll
            for (int b = 0; b < GB; b++) acc[b] = 0ull;
#pragma unroll
            for (int ii = 0; ii < 8; ii++) {
#pragma unroll
                for (int b = 0; b < GB; b++) {
                    ulonglong2 h2 = *(const ulonglong2*)(h0c + b * Hn + kb + ii * 4);
                    acc[b] = fma2(w0[2 * ii],     h2.x, acc[b]);
                    acc[b] = fma2(w0[2 * ii + 1], h2.y, acc[b]);
                }
            }
#pragma unroll
            for (int b = 0; b < GB; b++) {
                float2 f = upk(acc[b]);
                part0[kg * 256 + b * 32 + j] = f.x + f.y;
            }
            bar_sync(3, NCOMP);
            if (tid < 256) {
                float s0 = xpv, s1 = 0.f;
#pragma unroll
                for (int kk = 0; kk < NKG; kk += 2) {
                    s0 += part0[kk * 256 + tid];
                    s1 += part0[(kk + 1) * 256 + tid];
                }
                float hn = tanhf(s0 + s1);
                __stcg(&g_h0buf[cur][group][rb * Hn + rcol], hn);
                if (t + 1 < Tn) xpv = __ldg(g_xp + xbase + (size_t)(t + 1) * Hn);
            }
            bar_sync(3, NCOMP);
            if (tid == 0) st_rel(&f0g[slice], (unsigned)(t + 1));
        }

        if (t >= 1) {
            bar_sync(2, NTHR);   // shh1[cur] = h1_{t-2} ready

            // ---- phase B: mvB = W_hh1 . h1_{t-2}
#pragma unroll
            for (int b = 0; b < GB; b++) acc[b] = 0ull;
#pragma unroll
            for (int ii = 0; ii < 8; ii++) {
#pragma unroll
                for (int b = 0; b < GB; b++) {
                    ulonglong2 h2 = *(const ulonglong2*)(h1c + b * Hn + kb + ii * 4);
                    acc[b] = fma2(w1[2 * ii],     h2.x, acc[b]);
                    acc[b] = fma2(w1[2 * ii + 1], h2.y, acc[b]);
                }
            }
            // ---- mvC = W_ih1 . h0_{t-1}
            {
                const float* wr = wih1 + j * WSTRIDE + kb;
#pragma unroll
                for (int ii = 0; ii < 8; ii++) {
                    ulonglong2 w2 = *(const ulonglong2*)(wr + ii * 4);
#pragma unroll
                    for (int b = 0; b < GB; b++) {
                        ulonglong2 h2 = *(const ulonglong2*)(h0c + b * Hn + kb + ii * 4);
                        acc[b] = fma2(w2.x, h2.x, acc[b]);
                        acc[b] = fma2(w2.y, h2.y, acc[b]);
                    }
                }
            }
#pragma unroll
            for (int b = 0; b < GB; b++) {
                float2 f = upk(acc[b]);
                part1[kg * 256 + b * 32 + j] = f.x + f.y;
            }
            bar_sync(3, NCOMP);
            if (tid < 256) {
                float s0 = bias1, s1 = 0.f;
#pragma unroll
                for (int kk = 0; kk < NKG; kk += 2) {
                    s0 += part1[kk * 256 + tid];
                    s1 += part1[(kk + 1) * 256 + tid];
                }
                float hn = tanhf(s0 + s1);
                if (t < Tn) __stcg(&g_h1buf[cur][group][rb * Hn + rcol], hn);
                else        g_hT[(group * GB + rb) * Hn + rcol] = hn;
            }
            bar_sync(3, NCOMP);
            if (t < Tn && tid == 0) st_rel(&f1g[slice], (unsigned)t);
        }
    }
}

// ---------------- final FC ------------------------------------------------------
__global__ __launch_bounds__(128) void fc_kernel(
    const float* __restrict__ Wfc, const float* __restrict__ bfc,
    float* __restrict__ out)
{
    __shared__ float hs[Hn];
    const int b = blockIdx.x, tid = threadIdx.x;
    ((float4*)hs)[tid] = *(const float4*)&g_hT[b * Hn + tid * 4];
    __syncthreads();
    const float4* wr = (const float4*)(Wfc + (size_t)tid * Hn);
    float acc = 0.f;
#pragma unroll 8
    for (int i = 0; i < Hn / 4; i++) {
        float4 w = __ldg(&wr[i]);
        float4 h = ((const float4*)hs)[i];
        acc += w.x * h.x + w.y * h.y + w.z * h.z + w.w * h.w;
    }
    out[b * On + tid] = acc + bfc[tid];
}

// ---------------- launcher ------------------------------------------------------
extern "C" void kernel_launch(void* const* d_in, const int* in_sizes, int n_in,
                              void* d_out, int out_size)
{
    (void)in_sizes; (void)n_in; (void)out_size;
    const float* x     = (const float*)d_in[0];
    const float* W_ih0 = (const float*)d_in[1];
    const float* W_hh0 = (const float*)d_in[2];
    const float* b_ih0 = (const float*)d_in[3];
    const float* b_hh0 = (const float*)d_in[4];
    const float* h0_0  = (const float*)d_in[5];
    const float* W_ih1 = (const float*)d_in[6];
    const float* W_hh1 = (const float*)d_in[7];
    const float* b_ih1 = (const float*)d_in[8];
    const float* b_hh1 = (const float*)d_in[9];
    const float* h0_1  = (const float*)d_in[10];
    const float* W_fc  = (const float*)d_in[11];
    const float* b_fc  = (const float*)d_in[12];
    float* out = (float*)d_out;

    const int fused_smem =
        (SC * WSTRIDE + 4 * GB * Hn + 2 * NKG * 256) * sizeof(float);
    cudaFuncSetAttribute(fused_rnn, cudaFuncAttributeMaxDynamicSharedMemorySize, fused_smem);

    // xp0 = x @ W_ih0^T + b_ih0 + b_hh0  (block 0 also resets exchange flags)
    sgemm_xp<<<dim3((Bn * Tn) / 128, Hn / 128), 256>>>(x, W_ih0, b_ih0, b_hh0);

    // fused skewed two-layer recurrence, warp-specialized comm (R3 geometry)
    fused_rnn<<<NG * NS, NTHR, fused_smem>>>(W_hh0, W_ih1, W_hh1,
                                             b_ih1, b_hh1, h0_0, h0_1);

    // head
    fc_kernel<<<Bn, 128>>>(W_fc, b_fc, out);
}

// round 7
// speedup vs baseline: 1.3210x; 1.3210x over previous
#include <cuda_runtime.h>
#include <cstdint>
#include <cstddef>

// Problem dims
#define Bn 64
#define Tn 2048
#define Fn 256
#define Hn 512
#define On 128

// Fused recurrence partition: 8 groups x 8 batches, 16 slices x 32 cols = 128 CTAs
#define NG 8
#define GB 8
#define NS 16
#define NKG 16
#define KC 32
#define SC 32
#define NTHR 512
#define WSTRIDE 516   // padded W_ih1 row stride (16B-aligned)

// ---------------- static device workspaces -------------------------------------
__device__ __align__(128) float g_xp[(size_t)Bn * Tn * Hn];      // 256 MB input proj
__device__ __align__(128) float g_h0buf[2][NG][GB * Hn];         // parity-buffered h0
__device__ __align__(128) float g_h1buf[2][NG][GB * Hn];         // parity-buffered h1
__device__ __align__(128) float g_hT[Bn * Hn];
__device__ unsigned g_flags0[NG][NS];
__device__ unsigned g_flags1[NG][NS];

typedef unsigned long long u64t;

// ---------------- packed fp32x2 + sync helpers ----------------------------------
__device__ __forceinline__ u64t fma2(u64t a, u64t b, u64t c) {
    u64t d;
    asm("fma.rn.f32x2 %0, %1, %2, %3;" : "=l"(d) : "l"(a), "l"(b), "l"(c));
    return d;
}
__device__ __forceinline__ u64t pk2(float lo, float hi) {
    u64t r;
    asm("mov.b64 %0, {%1, %2};" : "=l"(r) : "f"(lo), "f"(hi));
    return r;
}
__device__ __forceinline__ float2 upk(u64t v) {
    float2 f;
    asm("mov.b64 {%0, %1}, %2;" : "=f"(f.x), "=f"(f.y) : "l"(v));
    return f;
}
__device__ __forceinline__ unsigned ld_acq(const unsigned* p) {
    unsigned v;
    asm volatile("ld.global.acquire.gpu.u32 %0, [%1];" : "=r"(v) : "l"(p));
    return v;
}
__device__ __forceinline__ void st_rel(unsigned* p, unsigned v) {
    asm volatile("st.global.release.gpu.u32 [%0], %1;" :: "l"(p), "r"(v) : "memory");
}
__device__ __forceinline__ unsigned smem_u32(const void* p) {
    unsigned a;
    asm("{ .reg .u64 t; cvta.to.shared.u64 t, %1; cvt.u32.u64 %0, t; }" : "=r"(a) : "l"(p));
    return a;
}
__device__ __forceinline__ void mbar_init(unsigned m, unsigned cnt) {
    asm volatile("mbarrier.init.shared.b64 [%0], %1;" :: "r"(m), "r"(cnt) : "memory");
}
__device__ __forceinline__ void mbar_expect_tx(unsigned m, unsigned bytes) {
    asm volatile("mbarrier.arrive.expect_tx.shared.b64 _, [%0], %1;" :: "r"(m), "r"(bytes) : "memory");
}
__device__ __forceinline__ void bulk_g2s(unsigned dst, const void* src, unsigned bytes, unsigned m) {
    asm volatile("cp.async.bulk.shared::cluster.global.mbarrier::complete_tx::bytes [%0], [%1], %2, [%3];"
                 :: "r"(dst), "l"(src), "r"(bytes), "r"(m) : "memory");
}
__device__ __forceinline__ void mbar_wait(unsigned m, int phase) {
    asm volatile(
        "{\n\t.reg .pred P;\n"
        "WL%=:\n\t"
        "mbarrier.try_wait.parity.acquire.cta.shared::cta.b64 P, [%0], %1, 0x989680;\n\t"
        "@P bra WD%=;\n\t"
        "bra WL%=;\n"
        "WD%=:\n\t}"
        :: "r"(m), "r"((unsigned)phase) : "memory");
}

// ---------------- GEMM1: g_xp[M,512] = x[M,256] * W_ih0[512,256]^T + b ----------
__global__ __launch_bounds__(256) void sgemm_xp(
    const float* __restrict__ A, const float* __restrict__ Wm,
    const float* __restrict__ b1, const float* __restrict__ b2)
{
    __shared__ float As[8][128];
    __shared__ float Ws[8][128];

    const int tid = threadIdx.x;
    if (blockIdx.x == 0 && blockIdx.y == 0 && tid < NG * NS) {
        ((unsigned*)g_flags0)[tid] = 0u;
        ((unsigned*)g_flags1)[tid] = 0u;
    }

    const int K = Fn;
    const int bm = blockIdx.x, bn = blockIdx.y;
    const int row = tid >> 1;
    const int kq = (tid & 1) * 4;
    const float* Ag = A + (size_t)(bm * 128 + row) * K + kq;
    const float* Wg = Wm + (size_t)(bn * 128 + row) * K + kq;
    const int tx = tid & 15, ty = tid >> 4;
    const int m0 = ty * 8, n0 = tx * 8;

    u64t acc[8][4];
#pragma unroll
    for (int i = 0; i < 8; i++)
#pragma unroll
        for (int j = 0; j < 4; j++) acc[i][j] = 0ull;

    float4 ap = *(const float4*)Ag;
    float4 wp = *(const float4*)Wg;
    const int nk = K >> 3;

    for (int kt = 0; kt < nk; kt++) {
        As[kq + 0][row] = ap.x; As[kq + 1][row] = ap.y;
        As[kq + 2][row] = ap.z; As[kq + 3][row] = ap.w;
        Ws[kq + 0][row] = wp.x; Ws[kq + 1][row] = wp.y;
        Ws[kq + 2][row] = wp.z; Ws[kq + 3][row] = wp.w;
        __syncthreads();
        if (kt + 1 < nk) {
            ap = *(const float4*)(Ag + (size_t)(kt + 1) * 8);
            wp = *(const float4*)(Wg + (size_t)(kt + 1) * 8);
        }
#pragma unroll
        for (int k = 0; k < 8; k++) {
            float4 a0 = *(const float4*)&As[k][m0];
            float4 a1 = *(const float4*)&As[k][m0 + 4];
            const u64t* bp = (const u64t*)&Ws[k][n0];
            u64t bv0 = bp[0], bv1 = bp[1], bv2 = bp[2], bv3 = bp[3];
            float av[8] = {a0.x, a0.y, a0.z, a0.w, a1.x, a1.y, a1.z, a1.w};
#pragma unroll
            for (int i = 0; i < 8; i++) {
                u64t ai = pk2(av[i], av[i]);
                acc[i][0] = fma2(ai, bv0, acc[i][0]);
                acc[i][1] = fma2(ai, bv1, acc[i][1]);
                acc[i][2] = fma2(ai, bv2, acc[i][2]);
                acc[i][3] = fma2(ai, bv3, acc[i][3]);
            }
        }
        __syncthreads();
    }

    const int gn = bn * 128 + n0;
    float bs[8];
#pragma unroll
    for (int j = 0; j < 8; j++) bs[j] = b1[gn + j] + b2[gn + j];
#pragma unroll
    for (int i = 0; i < 8; i++) {
        float* cp = g_xp + (size_t)(bm * 128 + m0 + i) * Hn + gn;
        float2 p0 = upk(acc[i][0]), p1 = upk(acc[i][1]);
        float2 p2 = upk(acc[i][2]), p3 = upk(acc[i][3]);
        *(float4*)cp       = make_float4(p0.x + bs[0], p0.y + bs[1], p1.x + bs[2], p1.y + bs[3]);
        *(float4*)(cp + 4) = make_float4(p2.x + bs[4], p2.y + bs[5], p3.x + bs[6], p3.y + bs[7]);
    }
}

// ---------------- fused, layer-1-skewed two-layer recurrence (R3 + fixes) -------
// Iteration t computes h0_t AND h1_{t-1}. Fixes over R3:
//  * mbarrier waits executed by tid 0 only, propagated via __syncthreads
//    (kills 16-warp try_wait serialization on one mbarrier address).
//  * f0 flag polls are prefetched before mvB and checked after it, hiding the
//    ~600-cycle L2 acquire round trip under compute.
__global__ __launch_bounds__(NTHR, 1) void fused_rnn(
    const float* __restrict__ Whh0, const float* __restrict__ Wih1,
    const float* __restrict__ Whh1,
    const float* __restrict__ bih1, const float* __restrict__ bhh1,
    const float* __restrict__ h00, const float* __restrict__ h01)
{
    extern __shared__ float sm[];
    float* wih1  = sm;                 // SC*WSTRIDE = 16512 floats
    float* shh0  = sm + SC * WSTRIDE;  // 2 x 4096 (parity)
    float* shh1  = shh0 + 2 * GB * Hn; // 2 x 4096 (parity)
    float* part0 = shh1 + 2 * GB * Hn; // NKG*256 = 4096
    float* part1 = part0 + NKG * 256;  // 4096
    __shared__ __align__(8) unsigned long long mbar[2];

    const int tid = threadIdx.x;
    const int slice = blockIdx.x & (NS - 1);
    const int group = blockIdx.x >> 4;
    const int j = tid & 31;
    const int kg = tid >> 5;
    const int col = slice * SC + j;
    const int kb = kg * KC;

    // recurrence weights into registers (32 floats per matrix per thread)
    u64t w0[16], w1[16];
    {
        const ulonglong2* p0 = (const ulonglong2*)(Whh0 + (size_t)col * Hn + kb);
        const ulonglong2* p1 = (const ulonglong2*)(Whh1 + (size_t)col * Hn + kb);
#pragma unroll
        for (int i = 0; i < 8; i++) {
            ulonglong2 a = p0[i]; w0[2 * i] = a.x; w0[2 * i + 1] = a.y;
            ulonglong2 b = p1[i]; w1[2 * i] = b.x; w1[2 * i + 1] = b.y;
        }
    }
    // W_ih1 slice into padded SMEM
    for (int idx = tid; idx < SC * Hn; idx += NTHR) {
        int r = idx >> 9, k = idx & 511;
        wih1[r * WSTRIDE + k] = Wih1[(size_t)(slice * SC + r) * Hn + k];
    }
    // preload: parity0 of shh0 = h00 (iter 0 input); parity1 of shh1 = h01
    for (int idx = tid; idx < GB * Hn; idx += NTHR) {
        shh0[idx] = h00[idx & 511];
        shh1[GB * Hn + idx] = h01[idx & 511];
    }

    const unsigned mb0 = smem_u32(&mbar[0]);
    const unsigned mb1 = smem_u32(&mbar[1]);
    const unsigned sh0a = smem_u32(shh0);
    const unsigned sh1a = smem_u32(shh1);
    const unsigned HBYTES = GB * Hn * 4;  // 16384
    if (tid == 0) {
        mbar_init(mb0, 1);
        mbar_init(mb1, 1);
        asm volatile("fence.proxy.async.shared::cta;" ::: "memory");
    }

    // reduce/publish role: thread tid<256 -> (batch rb, col rj)
    const int rb = tid >> 5, rj = tid & 31;          // valid for tid<256
    const int rcol = slice * SC + rj;
    const float bias1 = bih1[rcol] + bhh1[rcol];
    const size_t xbase = ((size_t)(group * GB + rb) * Tn) * Hn + rcol;
    float xpv = (tid < 256) ? __ldg(g_xp + xbase) : 0.f;
    unsigned* f0 = &g_flags0[group][0];
    unsigned* f1 = &g_flags1[group][0];
    __syncthreads();

    int ph0 = 0, ph1 = 0;
    u64t acc[8];

#pragma unroll 1
    for (int t = 0; t <= Tn; t++) {
        const int cur = t & 1, nxt = cur ^ 1;
        const float* h0c = shh0 + cur * (GB * Hn);
        const float* h1c = shh1 + cur * (GB * Hn);

        // shh0[cur] = h0_{t-1}: leader waits for the bulk copy, barrier propagates
        if (t > 0) {
            if (tid == 0) mbar_wait(mb0, ph0);
            ph0 ^= 1;
            __syncthreads();
        }

        if (t < Tn) {
            // ---- mv0 = W_hh0 . h0_{t-1}
#pragma unroll
            for (int b = 0; b < 8; b++) acc[b] = 0ull;
#pragma unroll
            for (int ii = 0; ii < 8; ii++) {
#pragma unroll
                for (int b = 0; b < 8; b++) {
                    ulonglong2 h2 = *(const ulonglong2*)(h0c + b * Hn + kb + ii * 4);
                    acc[b] = fma2(w0[2 * ii],     h2.x, acc[b]);
                    acc[b] = fma2(w0[2 * ii + 1], h2.y, acc[b]);
                }
            }
#pragma unroll
            for (int b = 0; b < 8; b++) {
                float2 f = upk(acc[b]);
                part0[kg * 256 + b * 32 + j] = f.x + f.y;
            }
            __syncthreads();
            if (tid < 256) {
                float s0 = xpv, s1 = 0.f;
#pragma unroll
                for (int kk = 0; kk < 16; kk += 2) {
                    s0 += part0[kk * 256 + tid];
                    s1 += part0[(kk + 1) * 256 + tid];
                }
                float hn = tanhf(s0 + s1);
                __stcg(&g_h0buf[cur][group][rb * Hn + rcol], hn);
                if (t + 1 < Tn) xpv = __ldg(g_xp + xbase + (size_t)(t + 1) * Hn);
            }
            __syncthreads();
            if (tid == 0) st_rel(&f0[slice], (unsigned)(t + 1));
        }

        if (t > 0) {
            // shh1[cur] = h1_{t-2}: leader waits (preloaded for t==1)
            if (t >= 2) {
                if (tid == 0) mbar_wait(mb1, ph1);
                ph1 ^= 1;
                __syncthreads();
            }

            // prefetch f0 polls (acquire loads) — latency hidden under mvB
            unsigned fv = 0xFFFFFFFFu;
            if (t < Tn && tid < 16) fv = ld_acq(&f0[tid]);

            // ---- mvB = W_hh1 . h1_{t-2}
#pragma unroll
            for (int b = 0; b < 8; b++) acc[b] = 0ull;
#pragma unroll
            for (int ii = 0; ii < 8; ii++) {
#pragma unroll
                for (int b = 0; b < 8; b++) {
                    ulonglong2 h2 = *(const ulonglong2*)(h1c + b * Hn + kb + ii * 4);
                    acc[b] = fma2(w1[2 * ii],     h2.x, acc[b]);
                    acc[b] = fma2(w1[2 * ii + 1], h2.y, acc[b]);
                }
            }

            // ---- kick h0_t -> shh0[nxt] bulk copy (poll results already in flight)
            if (t < Tn && tid < 32) {
                if (tid < 16) {
                    while (fv < (unsigned)(t + 1)) fv = ld_acq(&f0[tid]);
                }
                __syncwarp();
                if (tid == 0) {
                    mbar_expect_tx(mb0, HBYTES);
                    bulk_g2s(sh0a + nxt * HBYTES, &g_h0buf[cur][group][0], HBYTES, mb0);
                }
            }

            // ---- mvC = W_ih1 . h0_{t-1}, accumulated on top of mvB
            {
                const float* wr = wih1 + j * WSTRIDE + kb;
#pragma unroll
                for (int ii = 0; ii < 8; ii++) {
                    ulonglong2 w2 = *(const ulonglong2*)(wr + ii * 4);
#pragma unroll
                    for (int b = 0; b < 8; b++) {
                        ulonglong2 h2 = *(const ulonglong2*)(h0c + b * Hn + kb + ii * 4);
                        acc[b] = fma2(w2.x, h2.x, acc[b]);
                        acc[b] = fma2(w2.y, h2.y, acc[b]);
                    }
                }
            }
#pragma unroll
            for (int b = 0; b < 8; b++) {
                float2 f = upk(acc[b]);
                part1[kg * 256 + b * 32 + j] = f.x + f.y;
            }
            __syncthreads();
            if (tid < 256) {
                float s0 = bias1, s1 = 0.f;
#pragma unroll
                for (int kk = 0; kk < 16; kk += 2) {
                    s0 += part1[kk * 256 + tid];
                    s1 += part1[(kk + 1) * 256 + tid];
                }
                float hn = tanhf(s0 + s1);
                if (t < Tn) __stcg(&g_h1buf[cur][group][rb * Hn + rcol], hn);
                else        g_hT[(group * GB + rb) * Hn + rcol] = hn;
            }
            __syncthreads();
            if (t < Tn) {
                if (tid == 0) st_rel(&f1[slice], (unsigned)t);
                // kick h1_{t-1} -> shh1[nxt]; consumed after next iter's mv0
                if (tid < 32) {
                    if (tid < 16) { while (ld_acq(&f1[tid]) < (unsigned)t) {} }
                    __syncwarp();
                    if (tid == 0) {
                        mbar_expect_tx(mb1, HBYTES);
                        bulk_g2s(sh1a + nxt * HBYTES, &g_h1buf[cur][group][0], HBYTES, mb1);
                    }
                }
            }
        } else {
            // t == 0: kick the very first h0 copy
            if (tid < 32) {
                if (tid < 16) { while (ld_acq(&f0[tid]) < 1u) {} }
                __syncwarp();
                if (tid == 0) {
                    mbar_expect_tx(mb0, HBYTES);
                    bulk_g2s(sh0a + HBYTES, &g_h0buf[0][group][0], HBYTES, mb0);
                }
            }
        }
    }
}

// ---------------- final FC ------------------------------------------------------
__global__ __launch_bounds__(128) void fc_kernel(
    const float* __restrict__ Wfc, const float* __restrict__ bfc,
    float* __restrict__ out)
{
    __shared__ float hs[Hn];
    const int b = blockIdx.x, tid = threadIdx.x;
    ((float4*)hs)[tid] = *(const float4*)&g_hT[b * Hn + tid * 4];
    __syncthreads();
    const float4* wr = (const float4*)(Wfc + (size_t)tid * Hn);
    float acc = 0.f;
#pragma unroll 8
    for (int i = 0; i < Hn / 4; i++) {
        float4 w = __ldg(&wr[i]);
        float4 h = ((const float4*)hs)[i];
        acc += w.x * h.x + w.y * h.y + w.z * h.z + w.w * h.w;
    }
    out[b * On + tid] = acc + bfc[tid];
}

// ---------------- launcher ------------------------------------------------------
extern "C" void kernel_launch(void* const* d_in, const int* in_sizes, int n_in,
                              void* d_out, int out_size)
{
    (void)in_sizes; (void)n_in; (void)out_size;
    const float* x     = (const float*)d_in[0];
    const float* W_ih0 = (const float*)d_in[1];
    const float* W_hh0 = (const float*)d_in[2];
    const float* b_ih0 = (const float*)d_in[3];
    const float* b_hh0 = (const float*)d_in[4];
    const float* h0_0  = (const float*)d_in[5];
    const float* W_ih1 = (const float*)d_in[6];
    const float* W_hh1 = (const float*)d_in[7];
    const float* b_ih1 = (const float*)d_in[8];
    const float* b_hh1 = (const float*)d_in[9];
    const float* h0_1  = (const float*)d_in[10];
    const float* W_fc  = (const float*)d_in[11];
    const float* b_fc  = (const float*)d_in[12];
    float* out = (float*)d_out;

    const int fused_smem =
        (SC * WSTRIDE + 4 * GB * Hn + 2 * NKG * 256) * sizeof(float);
    cudaFuncSetAttribute(fused_rnn, cudaFuncAttributeMaxDynamicSharedMemorySize, fused_smem);

    // xp0 = x @ W_ih0^T + b_ih0 + b_hh0  (block 0 also resets exchange flags)
    sgemm_xp<<<dim3((Bn * Tn) / 128, Hn / 128), 256>>>(x, W_ih0, b_ih0, b_hh0);

    // fused skewed two-layer recurrence
    fused_rnn<<<NG * NS, NTHR, fused_smem>>>(W_hh0, W_ih1, W_hh1,
                                             b_ih1, b_hh1, h0_0, h0_1);

    // head
    fc_kernel<<<Bn, 128>>>(W_fc, b_fc, out);
}

// round 8
// speedup vs baseline: 1.3261x; 1.0039x over previous
#include <cuda_runtime.h>
#include <cstdint>
#include <cstddef>

// Problem dims
#define Bn 64
#define Tn 2048
#define Fn 256
#define Hn 512
#define On 128

// Fused recurrence partition: 8 groups x 8 batches, 16 slices x 32 cols = 128 CTAs
#define NG 8
#define GB 8
#define NS 16
#define NKG 16
#define KC 32
#define SC 32
#define NTHR 512
#define WSTRIDE 516   // padded W_ih1 row stride (16B-aligned)

// ---------------- static device workspaces -------------------------------------
__device__ __align__(128) float g_xp[(size_t)Bn * Tn * Hn];      // 256 MB input proj
__device__ __align__(128) float g_h0buf[2][NG][GB * Hn];         // parity-buffered h0
__device__ __align__(128) float g_h1buf[2][NG][GB * Hn];         // parity-buffered h1
__device__ __align__(128) float g_hT[Bn * Hn];
__device__ unsigned g_flags0[NG][NS];
__device__ unsigned g_flags1[NG][NS];

typedef unsigned long long u64t;

// ---------------- packed fp32x2 + sync helpers ----------------------------------
__device__ __forceinline__ u64t fma2(u64t a, u64t b, u64t c) {
    u64t d;
    asm("fma.rn.f32x2 %0, %1, %2, %3;" : "=l"(d) : "l"(a), "l"(b), "l"(c));
    return d;
}
__device__ __forceinline__ u64t pk2(float lo, float hi) {
    u64t r;
    asm("mov.b64 %0, {%1, %2};" : "=l"(r) : "f"(lo), "f"(hi));
    return r;
}
__device__ __forceinline__ float2 upk(u64t v) {
    float2 f;
    asm("mov.b64 {%0, %1}, %2;" : "=f"(f.x), "=f"(f.y) : "l"(v));
    return f;
}
__device__ __forceinline__ unsigned ld_acq(const unsigned* p) {
    unsigned v;
    asm volatile("ld.global.acquire.gpu.u32 %0, [%1];" : "=r"(v) : "l"(p));
    return v;
}
__device__ __forceinline__ void st_rel(unsigned* p, unsigned v) {
    asm volatile("st.global.release.gpu.u32 [%0], %1;" :: "l"(p), "r"(v) : "memory");
}
__device__ __forceinline__ unsigned smem_u32(const void* p) {
    unsigned a;
    asm("{ .reg .u64 t; cvta.to.shared.u64 t, %1; cvt.u32.u64 %0, t; }" : "=r"(a) : "l"(p));
    return a;
}
__device__ __forceinline__ void mbar_init(unsigned m, unsigned cnt) {
    asm volatile("mbarrier.init.shared.b64 [%0], %1;" :: "r"(m), "r"(cnt) : "memory");
}
__device__ __forceinline__ void mbar_expect_tx(unsigned m, unsigned bytes) {
    asm volatile("mbarrier.arrive.expect_tx.shared.b64 _, [%0], %1;" :: "r"(m), "r"(bytes) : "memory");
}
__device__ __forceinline__ void bulk_g2s(unsigned dst, const void* src, unsigned bytes, unsigned m) {
    asm volatile("cp.async.bulk.shared::cluster.global.mbarrier::complete_tx::bytes [%0], [%1], %2, [%3];"
                 :: "r"(dst), "l"(src), "r"(bytes), "r"(m) : "memory");
}
__device__ __forceinline__ void mbar_wait(unsigned m, int phase) {
    asm volatile(
        "{\n\t.reg .pred P;\n"
        "WL%=:\n\t"
        "mbarrier.try_wait.parity.acquire.cta.shared::cta.b64 P, [%0], %1, 0x989680;\n\t"
        "@P bra WD%=;\n\t"
        "bra WL%=;\n"
        "WD%=:\n\t}"
        :: "r"(m), "r"((unsigned)phase) : "memory");
}

// ---------------- GEMM1: g_xp[M,512] = x[M,256] * W_ih0[512,256]^T + b ----------
__global__ __launch_bounds__(256) void sgemm_xp(
    const float* __restrict__ A, const float* __restrict__ Wm,
    const float* __restrict__ b1, const float* __restrict__ b2)
{
    __shared__ float As[8][128];
    __shared__ float Ws[8][128];

    const int tid = threadIdx.x;
    if (blockIdx.x == 0 && blockIdx.y == 0 && tid < NG * NS) {
        ((unsigned*)g_flags0)[tid] = 0u;
        ((unsigned*)g_flags1)[tid] = 0u;
    }

    const int K = Fn;
    const int bm = blockIdx.x, bn = blockIdx.y;
    const int row = tid >> 1;
    const int kq = (tid & 1) * 4;
    const float* Ag = A + (size_t)(bm * 128 + row) * K + kq;
    const float* Wg = Wm + (size_t)(bn * 128 + row) * K + kq;
    const int tx = tid & 15, ty = tid >> 4;
    const int m0 = ty * 8, n0 = tx * 8;

    u64t acc[8][4];
#pragma unroll
    for (int i = 0; i < 8; i++)
#pragma unroll
        for (int j = 0; j < 4; j++) acc[i][j] = 0ull;

    float4 ap = *(const float4*)Ag;
    float4 wp = *(const float4*)Wg;
    const int nk = K >> 3;

    for (int kt = 0; kt < nk; kt++) {
        As[kq + 0][row] = ap.x; As[kq + 1][row] = ap.y;
        As[kq + 2][row] = ap.z; As[kq + 3][row] = ap.w;
        Ws[kq + 0][row] = wp.x; Ws[kq + 1][row] = wp.y;
        Ws[kq + 2][row] = wp.z; Ws[kq + 3][row] = wp.w;
        __syncthreads();
        if (kt + 1 < nk) {
            ap = *(const float4*)(Ag + (size_t)(kt + 1) * 8);
            wp = *(const float4*)(Wg + (size_t)(kt + 1) * 8);
        }
#pragma unroll
        for (int k = 0; k < 8; k++) {
            float4 a0 = *(const float4*)&As[k][m0];
            float4 a1 = *(const float4*)&As[k][m0 + 4];
            const u64t* bp = (const u64t*)&Ws[k][n0];
            u64t bv0 = bp[0], bv1 = bp[1], bv2 = bp[2], bv3 = bp[3];
            float av[8] = {a0.x, a0.y, a0.z, a0.w, a1.x, a1.y, a1.z, a1.w};
#pragma unroll
            for (int i = 0; i < 8; i++) {
                u64t ai = pk2(av[i], av[i]);
                acc[i][0] = fma2(ai, bv0, acc[i][0]);
                acc[i][1] = fma2(ai, bv1, acc[i][1]);
                acc[i][2] = fma2(ai, bv2, acc[i][2]);
                acc[i][3] = fma2(ai, bv3, acc[i][3]);
            }
        }
        __syncthreads();
    }

    const int gn = bn * 128 + n0;
    float bs[8];
#pragma unroll
    for (int j = 0; j < 8; j++) bs[j] = b1[gn + j] + b2[gn + j];
#pragma unroll
    for (int i = 0; i < 8; i++) {
        float* cp = g_xp + (size_t)(bm * 128 + m0 + i) * Hn + gn;
        float2 p0 = upk(acc[i][0]), p1 = upk(acc[i][1]);
        float2 p2 = upk(acc[i][2]), p3 = upk(acc[i][3]);
        *(float4*)cp       = make_float4(p0.x + bs[0], p0.y + bs[1], p1.x + bs[2], p1.y + bs[3]);
        *(float4*)(cp + 4) = make_float4(p2.x + bs[4], p2.y + bs[5], p3.x + bs[6], p3.y + bs[7]);
    }
}

// ---------------- fused, layer-1-skewed two-layer recurrence (R3 + fixes) -------
// Iteration t computes h0_t AND h1_{t-1}. Fixes over R3:
//  * mbarrier waits executed by tid 0 only, propagated via __syncthreads
//    (kills 16-warp try_wait serialization on one mbarrier address).
//  * f0 flag polls are prefetched before mvB and checked after it, hiding the
//    ~600-cycle L2 acquire round trip under compute.
__global__ __launch_bounds__(NTHR, 1) void fused_rnn(
    const float* __restrict__ Whh0, const float* __restrict__ Wih1,
    const float* __restrict__ Whh1,
    const float* __restrict__ bih1, const float* __restrict__ bhh1,
    const float* __restrict__ h00, const float* __restrict__ h01)
{
    extern __shared__ float sm[];
    float* wih1  = sm;                 // SC*WSTRIDE = 16512 floats
    float* shh0  = sm + SC * WSTRIDE;  // 2 x 4096 (parity)
    float* shh1  = shh0 + 2 * GB * Hn; // 2 x 4096 (parity)
    float* part0 = shh1 + 2 * GB * Hn; // NKG*256 = 4096
    float* part1 = part0 + NKG * 256;  // 4096
    __shared__ __align__(8) unsigned long long mbar[2];

    const int tid = threadIdx.x;
    const int slice = blockIdx.x & (NS - 1);
    const int group = blockIdx.x >> 4;
    const int j = tid & 31;
    const int kg = tid >> 5;
    const int col = slice * SC + j;
    const int kb = kg * KC;

    // recurrence weights into registers (32 floats per matrix per thread)
    u64t w0[16], w1[16];
    {
        const ulonglong2* p0 = (const ulonglong2*)(Whh0 + (size_t)col * Hn + kb);
        const ulonglong2* p1 = (const ulonglong2*)(Whh1 + (size_t)col * Hn + kb);
#pragma unroll
        for (int i = 0; i < 8; i++) {
            ulonglong2 a = p0[i]; w0[2 * i] = a.x; w0[2 * i + 1] = a.y;
            ulonglong2 b = p1[i]; w1[2 * i] = b.x; w1[2 * i + 1] = b.y;
        }
    }
    // W_ih1 slice into padded SMEM
    for (int idx = tid; idx < SC * Hn; idx += NTHR) {
        int r = idx >> 9, k = idx & 511;
        wih1[r * WSTRIDE + k] = Wih1[(size_t)(slice * SC + r) * Hn + k];
    }
    // preload: parity0 of shh0 = h00 (iter 0 input); parity1 of shh1 = h01
    for (int idx = tid; idx < GB * Hn; idx += NTHR) {
        shh0[idx] = h00[idx & 511];
        shh1[GB * Hn + idx] = h01[idx & 511];
    }

    const unsigned mb0 = smem_u32(&mbar[0]);
    const unsigned mb1 = smem_u32(&mbar[1]);
    const unsigned sh0a = smem_u32(shh0);
    const unsigned sh1a = smem_u32(shh1);
    const unsigned HBYTES = GB * Hn * 4;  // 16384
    if (tid == 0) {
        mbar_init(mb0, 1);
        mbar_init(mb1, 1);
        asm volatile("fence.proxy.async.shared::cta;" ::: "memory");
    }

    // reduce/publish role: thread tid<256 -> (batch rb, col rj)
    const int rb = tid >> 5, rj = tid & 31;          // valid for tid<256
    const int rcol = slice * SC + rj;
    const float bias1 = bih1[rcol] + bhh1[rcol];
    const size_t xbase = ((size_t)(group * GB + rb) * Tn) * Hn + rcol;
    float xpv = (tid < 256) ? __ldg(g_xp + xbase) : 0.f;
    unsigned* f0 = &g_flags0[group][0];
    unsigned* f1 = &g_flags1[group][0];
    __syncthreads();

    int ph0 = 0, ph1 = 0;
    u64t acc[8];

#pragma unroll 1
    for (int t = 0; t <= Tn; t++) {
        const int cur = t & 1, nxt = cur ^ 1;
        const float* h0c = shh0 + cur * (GB * Hn);
        const float* h1c = shh1 + cur * (GB * Hn);

        // shh0[cur] = h0_{t-1}: leader waits for the bulk copy, barrier propagates
        if (t > 0) {
            if (tid == 0) mbar_wait(mb0, ph0);
            ph0 ^= 1;
            __syncthreads();
        }

        if (t < Tn) {
            // ---- mv0 = W_hh0 . h0_{t-1}
#pragma unroll
            for (int b = 0; b < 8; b++) acc[b] = 0ull;
#pragma unroll
            for (int ii = 0; ii < 8; ii++) {
#pragma unroll
                for (int b = 0; b < 8; b++) {
                    ulonglong2 h2 = *(const ulonglong2*)(h0c + b * Hn + kb + ii * 4);
                    acc[b] = fma2(w0[2 * ii],     h2.x, acc[b]);
                    acc[b] = fma2(w0[2 * ii + 1], h2.y, acc[b]);
                }
            }
#pragma unroll
            for (int b = 0; b < 8; b++) {
                float2 f = upk(acc[b]);
                part0[kg * 256 + b * 32 + j] = f.x + f.y;
            }
            __syncthreads();
            if (tid < 256) {
                float s0 = xpv, s1 = 0.f;
#pragma unroll
                for (int kk = 0; kk < 16; kk += 2) {
                    s0 += part0[kk * 256 + tid];
                    s1 += part0[(kk + 1) * 256 + tid];
                }
                float hn = tanhf(s0 + s1);
                __stcg(&g_h0buf[cur][group][rb * Hn + rcol], hn);
                if (t + 1 < Tn) xpv = __ldg(g_xp + xbase + (size_t)(t + 1) * Hn);
            }
            __syncthreads();
            if (tid == 0) st_rel(&f0[slice], (unsigned)(t + 1));
        }

        if (t > 0) {
            // shh1[cur] = h1_{t-2}: leader waits (preloaded for t==1)
            if (t >= 2) {
                if (tid == 0) mbar_wait(mb1, ph1);
                ph1 ^= 1;
                __syncthreads();
            }

            // prefetch f0 polls (acquire loads) — latency hidden under mvB
            unsigned fv = 0xFFFFFFFFu;
            if (t < Tn && tid < 16) fv = ld_acq(&f0[tid]);

            // ---- mvB = W_hh1 . h1_{t-2}
#pragma unroll
            for (int b = 0; b < 8; b++) acc[b] = 0ull;
#pragma unroll
            for (int ii = 0; ii < 8; ii++) {
#pragma unroll
                for (int b = 0; b < 8; b++) {
                    ulonglong2 h2 = *(const ulonglong2*)(h1c + b * Hn + kb + ii * 4);
                    acc[b] = fma2(w1[2 * ii],     h2.x, acc[b]);
                    acc[b] = fma2(w1[2 * ii + 1], h2.y, acc[b]);
                }
            }

            // ---- kick h0_t -> shh0[nxt] bulk copy (poll results already in flight)
            if (t < Tn && tid < 32) {
                if (tid < 16) {
                    while (fv < (unsigned)(t + 1)) fv = ld_acq(&f0[tid]);
                }
                __syncwarp();
                if (tid == 0) {
                    mbar_expect_tx(mb0, HBYTES);
                    bulk_g2s(sh0a + nxt * HBYTES, &g_h0buf[cur][group][0], HBYTES, mb0);
                }
            }

            // ---- mvC = W_ih1 . h0_{t-1}, accumulated on top of mvB
            {
                const float* wr = wih1 + j * WSTRIDE + kb;
#pragma unroll
                for (int ii = 0; ii < 8; ii++) {
                    ulonglong2 w2 = *(const ulonglong2*)(wr + ii * 4);
#pragma unroll
                    for (int b = 0; b < 8; b++) {
                        ulonglong2 h2 = *(const ulonglong2*)(h0c + b * Hn + kb + ii * 4);
                        acc[b] = fma2(w2.x, h2.x, acc[b]);
                        acc[b] = fma2(w2.y, h2.y, acc[b]);
                    }
                }
            }
#pragma unroll
            for (int b = 0; b < 8; b++) {
                float2 f = upk(acc[b]);
                part1[kg * 256 + b * 32 + j] = f.x + f.y;
            }
            __syncthreads();
            if (tid < 256) {
                float s0 = bias1, s1 = 0.f;
#pragma unroll
                for (int kk = 0; kk < 16; kk += 2) {
                    s0 += part1[kk * 256 + tid];
                    s1 += part1[(kk + 1) * 256 + tid];
                }
                float hn = tanhf(s0 + s1);
                if (t < Tn) __stcg(&g_h1buf[cur][group][rb * Hn + rcol], hn);
                else        g_hT[(group * GB + rb) * Hn + rcol] = hn;
            }
            __syncthreads();
            if (t < Tn) {
                if (tid == 0) st_rel(&f1[slice], (unsigned)t);
                // kick h1_{t-1} -> shh1[nxt]; consumed after next iter's mv0
                if (tid < 32) {
                    if (tid < 16) { while (ld_acq(&f1[tid]) < (unsigned)t) {} }
                    __syncwarp();
                    if (tid == 0) {
                        mbar_expect_tx(mb1, HBYTES);
                        bulk_g2s(sh1a + nxt * HBYTES, &g_h1buf[cur][group][0], HBYTES, mb1);
                    }
                }
            }
        } else {
            // t == 0: kick the very first h0 copy
            if (tid < 32) {
                if (tid < 16) { while (ld_acq(&f0[tid]) < 1u) {} }
                __syncwarp();
                if (tid == 0) {
                    mbar_expect_tx(mb0, HBYTES);
                    bulk_g2s(sh0a + HBYTES, &g_h0buf[0][group][0], HBYTES, mb0);
                }
            }
        }
    }
}

// ---------------- final FC ------------------------------------------------------
__global__ __launch_bounds__(128) void fc_kernel(
    const float* __restrict__ Wfc, const float* __restrict__ bfc,
    float* __restrict__ out)
{
    __shared__ float hs[Hn];
    const int b = blockIdx.x, tid = threadIdx.x;
    ((float4*)hs)[tid] = *(const float4*)&g_hT[b * Hn + tid * 4];
    __syncthreads();
    const float4* wr = (const float4*)(Wfc + (size_t)tid * Hn);
    float acc = 0.f;
#pragma unroll 8
    for (int i = 0; i < Hn / 4; i++) {
        float4 w = __ldg(&wr[i]);
        float4 h = ((const float4*)hs)[i];
        acc += w.x * h.x + w.y * h.y + w.z * h.z + w.w * h.w;
    }
    out[b * On + tid] = acc + bfc[tid];
}

// ---------------- launcher ------------------------------------------------------
extern "C" void kernel_launch(void* const* d_in, const int* in_sizes, int n_in,
                              void* d_out, int out_size)
{
    (void)in_sizes; (void)n_in; (void)out_size;
    const float* x     = (const float*)d_in[0];
    const float* W_ih0 = (const float*)d_in[1];
    const float* W_hh0 = (const float*)d_in[2];
    const float* b_ih0 = (const float*)d_in[3];
    const float* b_hh0 = (const float*)d_in[4];
    const float* h0_0  = (const float*)d_in[5];
    const float* W_ih1 = (const float*)d_in[6];
    const float* W_hh1 = (const float*)d_in[7];
    const float* b_ih1 = (const float*)d_in[8];
    const float* b_hh1 = (const float*)d_in[9];
    const float* h0_1  = (const float*)d_in[10];
    const float* W_fc  = (const float*)d_in[11];
    const float* b_fc  = (const float*)d_in[12];
    float* out = (float*)d_out;

    const int fused_smem =
        (SC * WSTRIDE + 4 * GB * Hn + 2 * NKG * 256) * sizeof(float);
    cudaFuncSetAttribute(fused_rnn, cudaFuncAttributeMaxDynamicSharedMemorySize, fused_smem);

    // xp0 = x @ W_ih0^T + b_ih0 + b_hh0  (block 0 also resets exchange flags)
    sgemm_xp<<<dim3((Bn * Tn) / 128, Hn / 128), 256>>>(x, W_ih0, b_ih0, b_hh0);

    // fused skewed two-layer recurrence
    fused_rnn<<<NG * NS, NTHR, fused_smem>>>(W_hh0, W_ih1, W_hh1,
                                             b_ih1, b_hh1, h0_0, h0_1);

    // head
    fc_kernel<<<Bn, 128>>>(W_fc, b_fc, out);
}

// round 9
// speedup vs baseline: 1.8535x; 1.3977x over previous
#include <cuda_runtime.h>
#include <cstdint>
#include <cstddef>

// Problem dims
#define Bn 64
#define Tn 2048
#define Fn 256
#define Hn 512
#define On 128

// Fused recurrence partition: 8 groups x 8 batches, 16 slices x 32 cols = 128 CTAs
#define NG 8
#define GB 8
#define NS 16
#define NKG 16
#define KC 32
#define SC 32
#define NTHR 512
#define WSTRIDE 516   // padded W_ih1 row stride (16B-aligned)
#define SXF 2048      // floats per x slice buffer: [8 b][256 k]

// ---------------- static device workspaces -------------------------------------
__device__ __align__(128) float g_h0buf[2][NG][GB * Hn];         // parity-buffered h0
__device__ __align__(128) float g_h1buf[2][NG][GB * Hn];         // parity-buffered h1
__device__ __align__(128) float g_hT[Bn * Hn];
__device__ unsigned g_flags0[NG][NS];
__device__ unsigned g_flags1[NG][NS];

typedef unsigned long long u64t;

// ---------------- packed fp32x2 + sync helpers ----------------------------------
__device__ __forceinline__ u64t fma2(u64t a, u64t b, u64t c) {
    u64t d;
    asm("fma.rn.f32x2 %0, %1, %2, %3;" : "=l"(d) : "l"(a), "l"(b), "l"(c));
    return d;
}
__device__ __forceinline__ float2 upk(u64t v) {
    float2 f;
    asm("mov.b64 {%0, %1}, %2;" : "=f"(f.x), "=f"(f.y) : "l"(v));
    return f;
}
__device__ __forceinline__ unsigned ld_acq(const unsigned* p) {
    unsigned v;
    asm volatile("ld.global.acquire.gpu.u32 %0, [%1];" : "=r"(v) : "l"(p));
    return v;
}
__device__ __forceinline__ void st_rel(unsigned* p, unsigned v) {
    asm volatile("st.global.release.gpu.u32 [%0], %1;" :: "l"(p), "r"(v) : "memory");
}
__device__ __forceinline__ unsigned smem_u32(const void* p) {
    unsigned a;
    asm("{ .reg .u64 t; cvta.to.shared.u64 t, %1; cvt.u32.u64 %0, t; }" : "=r"(a) : "l"(p));
    return a;
}
__device__ __forceinline__ void mbar_init(unsigned m, unsigned cnt) {
    asm volatile("mbarrier.init.shared.b64 [%0], %1;" :: "r"(m), "r"(cnt) : "memory");
}
__device__ __forceinline__ void mbar_expect_tx(unsigned m, unsigned bytes) {
    asm volatile("mbarrier.arrive.expect_tx.shared.b64 _, [%0], %1;" :: "r"(m), "r"(bytes) : "memory");
}
__device__ __forceinline__ void bulk_g2s(unsigned dst, const void* src, unsigned bytes, unsigned m) {
    asm volatile("cp.async.bulk.shared::cluster.global.mbarrier::complete_tx::bytes [%0], [%1], %2, [%3];"
                 :: "r"(dst), "l"(src), "r"(bytes), "r"(m) : "memory");
}
__device__ __forceinline__ void mbar_wait(unsigned m, int phase) {
    asm volatile(
        "{\n\t.reg .pred P;\n"
        "WL%=:\n\t"
        "mbarrier.try_wait.parity.acquire.cta.shared::cta.b64 P, [%0], %1, 0x989680;\n\t"
        "@P bra WD%=;\n\t"
        "bra WL%=;\n"
        "WD%=:\n\t}"
        :: "r"(m), "r"((unsigned)phase) : "memory");
}

// ---------------- fused recurrence with inline input projection ------------------
// Exactly R3's structure (the only sub-12ms configuration), with sgemm_xp folded
// into phase A: xp_t = W_ih0 . x_t is accumulated into the mv0 partial sums from
// a register-resident W_ih0 chunk (16 floats/thread) and a double-buffered SMEM
// x slice (prefetched one step ahead, coalesced LDG.128 + STS.128 per thread).
// Flags are epoch-relative (base read at entry) so no reset kernel is needed.
__global__ __launch_bounds__(NTHR, 1) void fused_rnn(
    const float* __restrict__ x,
    const float* __restrict__ Wih0, const float* __restrict__ Whh0,
    const float* __restrict__ bih0, const float* __restrict__ bhh0,
    const float* __restrict__ Wih1, const float* __restrict__ Whh1,
    const float* __restrict__ bih1, const float* __restrict__ bhh1,
    const float* __restrict__ h00, const float* __restrict__ h01)
{
    extern __shared__ float sm[];
    float* wih1  = sm;                 // SC*WSTRIDE = 16512 floats
    float* shh0  = sm + SC * WSTRIDE;  // 2 x 4096 (parity)
    float* shh1  = shh0 + 2 * GB * Hn; // 2 x 4096 (parity)
    float* part0 = shh1 + 2 * GB * Hn; // NKG*256 = 4096
    float* part1 = part0 + NKG * 256;  // 4096
    float* sx    = part1 + NKG * 256;  // 2 x SXF (parity-buffered x slice)
    __shared__ __align__(8) unsigned long long mbar[2];
    __shared__ unsigned sbase[2];

    const int tid = threadIdx.x;
    const int slice = blockIdx.x & (NS - 1);
    const int group = blockIdx.x >> 4;
    const int j = tid & 31;
    const int kg = tid >> 5;
    const int col = slice * SC + j;
    const int kb = kg * KC;

    // recurrence weights into registers: Whh0/Whh1 32 floats each, Wih0 16 floats
    u64t w0[16], w1[16], wx[8];
    {
        const ulonglong2* p0 = (const ulonglong2*)(Whh0 + (size_t)col * Hn + kb);
        const ulonglong2* p1 = (const ulonglong2*)(Whh1 + (size_t)col * Hn + kb);
#pragma unroll
        for (int i = 0; i < 8; i++) {
            ulonglong2 a = p0[i]; w0[2 * i] = a.x; w0[2 * i + 1] = a.y;
            ulonglong2 b = p1[i]; w1[2 * i] = b.x; w1[2 * i + 1] = b.y;
        }
        const ulonglong2* px = (const ulonglong2*)(Wih0 + (size_t)col * Fn + kg * 16);
#pragma unroll
        for (int i = 0; i < 4; i++) {
            ulonglong2 a = px[i]; wx[2 * i] = a.x; wx[2 * i + 1] = a.y;
        }
    }
    // W_ih1 slice into padded SMEM
    for (int idx = tid; idx < SC * Hn; idx += NTHR) {
        int r = idx >> 9, k = idx & 511;
        wih1[r * WSTRIDE + k] = Wih1[(size_t)(slice * SC + r) * Hn + k];
    }
    // preload: parity0 of shh0 = h00 (iter 0 input); parity1 of shh1 = h01
    for (int idx = tid; idx < GB * Hn; idx += NTHR) {
        shh0[idx] = h00[idx & 511];
        shh1[GB * Hn + idx] = h01[idx & 511];
    }

    // x staging role: all 512 threads own one float4 of the [8 b][256 k] slice
    const int xb_b = tid >> 6;            // batch within group
    const int xb_k = (tid & 63) * 4;      // k offset
    const float* xg = x + ((size_t)(group * GB + xb_b) * Tn) * Fn + xb_k;
    const int xsoff = xb_b * 256 + xb_k;
    // preload x[:,0,:] into sx parity 0
    *(float4*)(sx + xsoff) = *(const float4*)xg;

    const unsigned mb0 = smem_u32(&mbar[0]);
    const unsigned mb1 = smem_u32(&mbar[1]);
    const unsigned sh0a = smem_u32(shh0);
    const unsigned sh1a = smem_u32(shh1);
    const unsigned HBYTES = GB * Hn * 4;  // 16384
    if (tid == 0) {
        mbar_init(mb0, 1);
        mbar_init(mb1, 1);
        asm volatile("fence.proxy.async.shared::cta;" ::: "memory");
        // epoch bases: flags are uniform at launch (previous launch fully drained)
        sbase[0] = *(volatile unsigned*)&g_flags0[group][slice];
        sbase[1] = *(volatile unsigned*)&g_flags1[group][slice];
    }

    // reduce/publish role: thread tid<256 -> (batch rb, col rj)
    const int rb = tid >> 5, rj = tid & 31;          // valid for tid<256
    const int rcol = slice * SC + rj;
    const float bias0 = bih0[rcol] + bhh0[rcol];
    const float bias1 = bih1[rcol] + bhh1[rcol];
    unsigned* f0 = &g_flags0[group][0];
    unsigned* f1 = &g_flags1[group][0];
    __syncthreads();

    const unsigned base0 = sbase[0], base1 = sbase[1];
    int ph0 = 0, ph1 = 0;
    u64t acc[8];

#pragma unroll 1
    for (int t = 0; t <= Tn; t++) {
        const int cur = t & 1, nxt = cur ^ 1;
        const float* h0c = shh0 + cur * (GB * Hn);
        const float* h1c = shh1 + cur * (GB * Hn);

        // shh0[cur] = h0_{t-1}: wait for the bulk copy issued last iteration
        if (t > 0) { mbar_wait(mb0, ph0); ph0 ^= 1; }

        if (t < Tn) {
            // prefetch x[:,t+1,:] (consumed next step; DRAM latency hidden by mv0)
            float4 xf;
            const bool havex = (t + 1 < Tn);
            if (havex) xf = *(const float4*)(xg + (size_t)(t + 1) * Fn);

            // ---- mv0 = W_hh0 . h0_{t-1}  (+ xp_t = W_ih0 . x_t folded in)
#pragma unroll
            for (int b = 0; b < 8; b++) acc[b] = 0ull;
#pragma unroll
            for (int ii = 0; ii < 8; ii++) {
#pragma unroll
                for (int b = 0; b < 8; b++) {
                    ulonglong2 h2 = *(const ulonglong2*)(h0c + b * Hn + kb + ii * 4);
                    acc[b] = fma2(w0[2 * ii],     h2.x, acc[b]);
                    acc[b] = fma2(w0[2 * ii + 1], h2.y, acc[b]);
                }
            }
            {
                const float* sxc = sx + cur * SXF + kg * 16;
#pragma unroll
                for (int b = 0; b < 8; b++) {
                    const ulonglong2* xp2 = (const ulonglong2*)(sxc + b * 256);
#pragma unroll
                    for (int q = 0; q < 4; q++) {
                        ulonglong2 v = xp2[q];
                        acc[b] = fma2(wx[2 * q],     v.x, acc[b]);
                        acc[b] = fma2(wx[2 * q + 1], v.y, acc[b]);
                    }
                }
            }
#pragma unroll
            for (int b = 0; b < 8; b++) {
                float2 f = upk(acc[b]);
                part0[kg * 256 + b * 32 + j] = f.x + f.y;
            }
            __syncthreads();
            if (tid < 256) {
                float s0 = bias0, s1 = 0.f;
#pragma unroll
                for (int kk = 0; kk < 16; kk += 2) {
                    s0 += part0[kk * 256 + tid];
                    s1 += part0[(kk + 1) * 256 + tid];
                }
                float hn = tanhf(s0 + s1);
                __stcg(&g_h0buf[cur][group][rb * Hn + rcol], hn);
            }
            __syncthreads();
            // stage prefetched x into sx[nxt] (read after next iter's barriers)
            if (havex) *(float4*)(sx + nxt * SXF + xsoff) = xf;
            if (tid == 0) st_rel(&f0[slice], base0 + (unsigned)(t + 1));
        }

        if (t > 0) {
            // shh1[cur] = h1_{t-2} (preloaded for t==1, bulk-copied for t>=2)
            if (t >= 2) { mbar_wait(mb1, ph1); ph1 ^= 1; }

            // ---- mvB = W_hh1 . h1_{t-2}
#pragma unroll
            for (int b = 0; b < 8; b++) acc[b] = 0ull;
#pragma unroll
            for (int ii = 0; ii < 8; ii++) {
#pragma unroll
                for (int b = 0; b < 8; b++) {
                    ulonglong2 h2 = *(const ulonglong2*)(h1c + b * Hn + kb + ii * 4);
                    acc[b] = fma2(w1[2 * ii],     h2.x, acc[b]);
                    acc[b] = fma2(w1[2 * ii + 1], h2.y, acc[b]);
                }
            }

            // ---- kick h0_t -> shh0[nxt] bulk copy (hidden under mvC)
            if (t < Tn && tid < 32) {
                if (tid < 16) {
                    while (ld_acq(&f0[tid]) < base0 + (unsigned)(t + 1)) {}
                }
                __syncwarp();
                if (tid == 0) {
                    mbar_expect_tx(mb0, HBYTES);
                    bulk_g2s(sh0a + nxt * HBYTES, &g_h0buf[cur][group][0], HBYTES, mb0);
                }
            }

            // ---- mvC = W_ih1 . h0_{t-1}, accumulated on top of mvB
            {
                const float* wr = wih1 + j * WSTRIDE + kb;
#pragma unroll
                for (int ii = 0; ii < 8; ii++) {
                    ulonglong2 w2 = *(const ulonglong2*)(wr + ii * 4);
#pragma unroll
                    for (int b = 0; b < 8; b++) {
                        ulonglong2 h2 = *(const ulonglong2*)(h0c + b * Hn + kb + ii * 4);
                        acc[b] = fma2(w2.x, h2.x, acc[b]);
                        acc[b] = fma2(w2.y, h2.y, acc[b]);
                    }
                }
            }
#pragma unroll
            for (int b = 0; b < 8; b++) {
                float2 f = upk(acc[b]);
                part1[kg * 256 + b * 32 + j] = f.x + f.y;
            }
            __syncthreads();
            if (tid < 256) {
                float s0 = bias1, s1 = 0.f;
#pragma unroll
                for (int kk = 0; kk < 16; kk += 2) {
                    s0 += part1[kk * 256 + tid];
                    s1 += part1[(kk + 1) * 256 + tid];
                }
                float hn = tanhf(s0 + s1);
                if (t < Tn) __stcg(&g_h1buf[cur][group][rb * Hn + rcol], hn);
                else        g_hT[(group * GB + rb) * Hn + rcol] = hn;
            }
            __syncthreads();
            if (t < Tn) {
                if (tid == 0) st_rel(&f1[slice], base1 + (unsigned)t);
                // kick h1_{t-1} -> shh1[nxt]; consumed after next iter's mv0
                if (tid < 32) {
                    if (tid < 16) {
                        while (ld_acq(&f1[tid]) < base1 + (unsigned)t) {}
                    }
                    __syncwarp();
                    if (tid == 0) {
                        mbar_expect_tx(mb1, HBYTES);
                        bulk_g2s(sh1a + nxt * HBYTES, &g_h1buf[cur][group][0], HBYTES, mb1);
                    }
                }
            }
        } else {
            // t == 0: kick the very first h0 copy
            if (tid < 32) {
                if (tid < 16) {
                    while (ld_acq(&f0[tid]) < base0 + 1u) {}
                }
                __syncwarp();
                if (tid == 0) {
                    mbar_expect_tx(mb0, HBYTES);
                    bulk_g2s(sh0a + HBYTES, &g_h0buf[0][group][0], HBYTES, mb0);
                }
            }
        }
    }
}

// ---------------- final FC ------------------------------------------------------
__global__ __launch_bounds__(128) void fc_kernel(
    const float* __restrict__ Wfc, const float* __restrict__ bfc,
    float* __restrict__ out)
{
    __shared__ float hs[Hn];
    const int b = blockIdx.x, tid = threadIdx.x;
    ((float4*)hs)[tid] = *(const float4*)&g_hT[b * Hn + tid * 4];
    __syncthreads();
    const float4* wr = (const float4*)(Wfc + (size_t)tid * Hn);
    float acc = 0.f;
#pragma unroll 8
    for (int i = 0; i < Hn / 4; i++) {
        float4 w = __ldg(&wr[i]);
        float4 h = ((const float4*)hs)[i];
        acc += w.x * h.x + w.y * h.y + w.z * h.z + w.w * h.w;
    }
    out[b * On + tid] = acc + bfc[tid];
}

// ---------------- launcher ------------------------------------------------------
extern "C" void kernel_launch(void* const* d_in, const int* in_sizes, int n_in,
                              void* d_out, int out_size)
{
    (void)in_sizes; (void)n_in; (void)out_size;
    const float* x     = (const float*)d_in[0];
    const float* W_ih0 = (const float*)d_in[1];
    const float* W_hh0 = (const float*)d_in[2];
    const float* b_ih0 = (const float*)d_in[3];
    const float* b_hh0 = (const float*)d_in[4];
    const float* h0_0  = (const float*)d_in[5];
    const float* W_ih1 = (const float*)d_in[6];
    const float* W_hh1 = (const float*)d_in[7];
    const float* b_ih1 = (const float*)d_in[8];
    const float* b_hh1 = (const float*)d_in[9];
    const float* h0_1  = (const float*)d_in[10];
    const float* W_fc  = (const float*)d_in[11];
    const float* b_fc  = (const float*)d_in[12];
    float* out = (float*)d_out;

    const int fused_smem =
        (SC * WSTRIDE + 4 * GB * Hn + 2 * NKG * 256 + 2 * SXF) * sizeof(float);
    cudaFuncSetAttribute(fused_rnn, cudaFuncAttributeMaxDynamicSharedMemorySize, fused_smem);

    // fused skewed two-layer recurrence with inline input projection
    fused_rnn<<<NG * NS, NTHR, fused_smem>>>(
        x, W_ih0, W_hh0, b_ih0, b_hh0,
        W_ih1, W_hh1, b_ih1, b_hh1, h0_0, h0_1);

    // head
    fc_kernel<<<Bn, 128>>>(W_fc, b_fc, out);
}

// round 10
// speedup vs baseline: 2.1303x; 1.1493x over previous
#include <cuda_runtime.h>
#include <cstdint>
#include <cstddef>

// Problem dims
#define Bn 64
#define Tn 2048
#define Fn 256
#define Hn 512
#define On 128

// Fused recurrence partition: 8 groups x 8 batches, 16 slices x 32 cols = 128 CTAs
#define NG 8
#define GB 8
#define NS 16
#define NKG 16
#define KC 32
#define SC 32
#define NTHR 512
#define WSTRIDE 516   // padded W_ih1 row stride (16B-aligned)

// ---------------- static device workspaces -------------------------------------
__device__ __align__(128) float g_xp[(size_t)Bn * Tn * Hn];      // 256 MB input proj
__device__ __align__(128) float g_h0buf[2][NG][GB * Hn];         // parity-buffered h0
__device__ __align__(128) float g_h1buf[2][NG][GB * Hn];         // parity-buffered h1
__device__ __align__(128) float g_hT[Bn * Hn];
__device__ unsigned g_flags0[NG][NS];
__device__ unsigned g_flags1[NG][NS];

typedef unsigned long long u64t;

// ---------------- packed fp32x2 + sync helpers ----------------------------------
__device__ __forceinline__ u64t fma2(u64t a, u64t b, u64t c) {
    u64t d;
    asm("fma.rn.f32x2 %0, %1, %2, %3;" : "=l"(d) : "l"(a), "l"(b), "l"(c));
    return d;
}
__device__ __forceinline__ u64t pk2(float lo, float hi) {
    u64t r;
    asm("mov.b64 %0, {%1, %2};" : "=l"(r) : "f"(lo), "f"(hi));
    return r;
}
__device__ __forceinline__ float2 upk(u64t v) {
    float2 f;
    asm("mov.b64 {%0, %1}, %2;" : "=f"(f.x), "=f"(f.y) : "l"(v));
    return f;
}
__device__ __forceinline__ unsigned ld_acq(const unsigned* p) {
    unsigned v;
    asm volatile("ld.global.acquire.gpu.u32 %0, [%1];" : "=r"(v) : "l"(p));
    return v;
}
__device__ __forceinline__ void st_rel(unsigned* p, unsigned v) {
    asm volatile("st.global.release.gpu.u32 [%0], %1;" :: "l"(p), "r"(v) : "memory");
}
__device__ __forceinline__ unsigned smem_u32(const void* p) {
    unsigned a;
    asm("{ .reg .u64 t; cvta.to.shared.u64 t, %1; cvt.u32.u64 %0, t; }" : "=r"(a) : "l"(p));
    return a;
}
__device__ __forceinline__ void mbar_init(unsigned m, unsigned cnt) {
    asm volatile("mbarrier.init.shared.b64 [%0], %1;" :: "r"(m), "r"(cnt) : "memory");
}
__device__ __forceinline__ void mbar_expect_tx(unsigned m, unsigned bytes) {
    asm volatile("mbarrier.arrive.expect_tx.shared.b64 _, [%0], %1;" :: "r"(m), "r"(bytes) : "memory");
}
__device__ __forceinline__ void bulk_g2s(unsigned dst, const void* src, unsigned bytes, unsigned m) {
    asm volatile("cp.async.bulk.shared::cluster.global.mbarrier::complete_tx::bytes [%0], [%1], %2, [%3];"
                 :: "r"(dst), "l"(src), "r"(bytes), "r"(m) : "memory");
}
__device__ __forceinline__ void mbar_wait(unsigned m, int phase) {
    asm volatile(
        "{\n\t.reg .pred P;\n"
        "WL%=:\n\t"
        "mbarrier.try_wait.parity.acquire.cta.shared::cta.b64 P, [%0], %1, 0x989680;\n\t"
        "@P bra WD%=;\n\t"
        "bra WL%=;\n"
        "WD%=:\n\t}"
        :: "r"(m), "r"((unsigned)phase) : "memory");
}
// per-warp elected wait: lane 0 polls the mbarrier, __syncwarp propagates.
__device__ __forceinline__ void mbar_wait_warp(unsigned m, int phase, int lane0) {
    if (lane0) mbar_wait(m, phase);
    __syncwarp();
}

// ---------------- GEMM1: g_xp[M,512] = x[M,256] * W_ih0[512,256]^T + b ----------
__global__ __launch_bounds__(256) void sgemm_xp(
    const float* __restrict__ A, const float* __restrict__ Wm,
    const float* __restrict__ b1, const float* __restrict__ b2)
{
    __shared__ float As[8][128];
    __shared__ float Ws[8][128];

    const int tid = threadIdx.x;
    if (blockIdx.x == 0 && blockIdx.y == 0 && tid < NG * NS) {
        ((unsigned*)g_flags0)[tid] = 0u;
        ((unsigned*)g_flags1)[tid] = 0u;
    }

    const int K = Fn;
    const int bm = blockIdx.x, bn = blockIdx.y;
    const int row = tid >> 1;
    const int kq = (tid & 1) * 4;
    const float* Ag = A + (size_t)(bm * 128 + row) * K + kq;
    const float* Wg = Wm + (size_t)(bn * 128 + row) * K + kq;
    const int tx = tid & 15, ty = tid >> 4;
    const int m0 = ty * 8, n0 = tx * 8;

    u64t acc[8][4];
#pragma unroll
    for (int i = 0; i < 8; i++)
#pragma unroll
        for (int j = 0; j < 4; j++) acc[i][j] = 0ull;

    float4 ap = *(const float4*)Ag;
    float4 wp = *(const float4*)Wg;
    const int nk = K >> 3;

    for (int kt = 0; kt < nk; kt++) {
        As[kq + 0][row] = ap.x; As[kq + 1][row] = ap.y;
        As[kq + 2][row] = ap.z; As[kq + 3][row] = ap.w;
        Ws[kq + 0][row] = wp.x; Ws[kq + 1][row] = wp.y;
        Ws[kq + 2][row] = wp.z; Ws[kq + 3][row] = wp.w;
        __syncthreads();
        if (kt + 1 < nk) {
            ap = *(const float4*)(Ag + (size_t)(kt + 1) * 8);
            wp = *(const float4*)(Wg + (size_t)(kt + 1) * 8);
        }
#pragma unroll
        for (int k = 0; k < 8; k++) {
            float4 a0 = *(const float4*)&As[k][m0];
            float4 a1 = *(const float4*)&As[k][m0 + 4];
            const u64t* bp = (const u64t*)&Ws[k][n0];
            u64t bv0 = bp[0], bv1 = bp[1], bv2 = bp[2], bv3 = bp[3];
            float av[8] = {a0.x, a0.y, a0.z, a0.w, a1.x, a1.y, a1.z, a1.w};
#pragma unroll
            for (int i = 0; i < 8; i++) {
                u64t ai = pk2(av[i], av[i]);
                acc[i][0] = fma2(ai, bv0, acc[i][0]);
                acc[i][1] = fma2(ai, bv1, acc[i][1]);
                acc[i][2] = fma2(ai, bv2, acc[i][2]);
                acc[i][3] = fma2(ai, bv3, acc[i][3]);
            }
        }
        __syncthreads();
    }

    const int gn = bn * 128 + n0;
    float bs[8];
#pragma unroll
    for (int j = 0; j < 8; j++) bs[j] = b1[gn + j] + b2[gn + j];
#pragma unroll
    for (int i = 0; i < 8; i++) {
        float* cp = g_xp + (size_t)(bm * 128 + m0 + i) * Hn + gn;
        float2 p0 = upk(acc[i][0]), p1 = upk(acc[i][1]);
        float2 p2 = upk(acc[i][2]), p3 = upk(acc[i][3]);
        *(float4*)cp       = make_float4(p0.x + bs[0], p0.y + bs[1], p1.x + bs[2], p1.y + bs[3]);
        *(float4*)(cp + 4) = make_float4(p2.x + bs[4], p2.y + bs[5], p3.x + bs[6], p3.y + bs[7]);
    }
}

// ---------------- fused, layer-1-skewed two-layer recurrence (R3 + warp-wait) ---
// Iteration t computes h0_t AND h1_{t-1}; both need only values exchanged during
// iteration t-1, so all cross-CTA latency hides behind compute.
// Single change vs R3: mbarrier waits are executed by one lane per warp
// (mbar_wait_warp) instead of all 512 threads, cutting same-address try_wait
// traffic 32x. No other changes.
__global__ __launch_bounds__(NTHR, 1) void fused_rnn(
    const float* __restrict__ Whh0, const float* __restrict__ Wih1,
    const float* __restrict__ Whh1,
    const float* __restrict__ bih1, const float* __restrict__ bhh1,
    const float* __restrict__ h00, const float* __restrict__ h01)
{
    extern __shared__ float sm[];
    float* wih1  = sm;                 // SC*WSTRIDE = 16512 floats
    float* shh0  = sm + SC * WSTRIDE;  // 2 x 4096 (parity)
    float* shh1  = shh0 + 2 * GB * Hn; // 2 x 4096 (parity)
    float* part0 = shh1 + 2 * GB * Hn; // NKG*256 = 4096
    float* part1 = part0 + NKG * 256;  // 4096
    __shared__ __align__(8) unsigned long long mbar[2];

    const int tid = threadIdx.x;
    const int slice = blockIdx.x & (NS - 1);
    const int group = blockIdx.x >> 4;
    const int j = tid & 31;
    const int kg = tid >> 5;
    const int col = slice * SC + j;
    const int kb = kg * KC;
    const int lane0 = ((tid & 31) == 0);

    // recurrence weights into registers (32 floats per matrix per thread)
    u64t w0[16], w1[16];
    {
        const ulonglong2* p0 = (const ulonglong2*)(Whh0 + (size_t)col * Hn + kb);
        const ulonglong2* p1 = (const ulonglong2*)(Whh1 + (size_t)col * Hn + kb);
#pragma unroll
        for (int i = 0; i < 8; i++) {
            ulonglong2 a = p0[i]; w0[2 * i] = a.x; w0[2 * i + 1] = a.y;
            ulonglong2 b = p1[i]; w1[2 * i] = b.x; w1[2 * i + 1] = b.y;
        }
    }
    // W_ih1 slice into padded SMEM
    for (int idx = tid; idx < SC * Hn; idx += NTHR) {
        int r = idx >> 9, k = idx & 511;
        wih1[r * WSTRIDE + k] = Wih1[(size_t)(slice * SC + r) * Hn + k];
    }
    // preload: parity0 of shh0 = h00 (iter 0 input); parity1 of shh1 = h01
    for (int idx = tid; idx < GB * Hn; idx += NTHR) {
        shh0[idx] = h00[idx & 511];
        shh1[GB * Hn + idx] = h01[idx & 511];
    }

    const unsigned mb0 = smem_u32(&mbar[0]);
    const unsigned mb1 = smem_u32(&mbar[1]);
    const unsigned sh0a = smem_u32(shh0);
    const unsigned sh1a = smem_u32(shh1);
    const unsigned HBYTES = GB * Hn * 4;  // 16384
    if (tid == 0) {
        mbar_init(mb0, 1);
        mbar_init(mb1, 1);
        asm volatile("fence.proxy.async.shared::cta;" ::: "memory");
    }

    // reduce/publish role: thread tid<256 -> (batch rb, col rj)
    const int rb = tid >> 5, rj = tid & 31;          // valid for tid<256
    const int rcol = slice * SC + rj;
    const float bias1 = bih1[rcol] + bhh1[rcol];
    const size_t xbase = ((size_t)(group * GB + rb) * Tn) * Hn + rcol;
    float xpv = (tid < 256) ? __ldg(g_xp + xbase) : 0.f;
    unsigned* f0 = &g_flags0[group][0];
    unsigned* f1 = &g_flags1[group][0];
    __syncthreads();

    int ph0 = 0, ph1 = 0;
    u64t acc[8];

#pragma unroll 1
    for (int t = 0; t <= Tn; t++) {
        const int cur = t & 1, nxt = cur ^ 1;
        const float* h0c = shh0 + cur * (GB * Hn);
        const float* h1c = shh1 + cur * (GB * Hn);

        // shh0[cur] = h0_{t-1}: per-warp elected wait for the bulk copy
        if (t > 0) { mbar_wait_warp(mb0, ph0, lane0); ph0 ^= 1; }

        if (t < Tn) {
            // ---- mv0 = W_hh0 . h0_{t-1}
#pragma unroll
            for (int b = 0; b < 8; b++) acc[b] = 0ull;
#pragma unroll
            for (int ii = 0; ii < 8; ii++) {
#pragma unroll
                for (int b = 0; b < 8; b++) {
                    ulonglong2 h2 = *(const ulonglong2*)(h0c + b * Hn + kb + ii * 4);
                    acc[b] = fma2(w0[2 * ii],     h2.x, acc[b]);
                    acc[b] = fma2(w0[2 * ii + 1], h2.y, acc[b]);
                }
            }
#pragma unroll
            for (int b = 0; b < 8; b++) {
                float2 f = upk(acc[b]);
                part0[kg * 256 + b * 32 + j] = f.x + f.y;
            }
            __syncthreads();
            if (tid < 256) {
                float s0 = xpv, s1 = 0.f;
#pragma unroll
                for (int kk = 0; kk < 16; kk += 2) {
                    s0 += part0[kk * 256 + tid];
                    s1 += part0[(kk + 1) * 256 + tid];
                }
                float hn = tanhf(s0 + s1);
                __stcg(&g_h0buf[cur][group][rb * Hn + rcol], hn);
                if (t + 1 < Tn) xpv = __ldg(g_xp + xbase + (size_t)(t + 1) * Hn);
            }
            __syncthreads();
            if (tid == 0) st_rel(&f0[slice], (unsigned)(t + 1));
        }

        if (t > 0) {
            // shh1[cur] = h1_{t-2} (preloaded for t==1, bulk-copied for t>=2)
            if (t >= 2) { mbar_wait_warp(mb1, ph1, lane0); ph1 ^= 1; }

            // ---- mvB = W_hh1 . h1_{t-2}
#pragma unroll
            for (int b = 0; b < 8; b++) acc[b] = 0ull;
#pragma unroll
            for (int ii = 0; ii < 8; ii++) {
#pragma unroll
                for (int b = 0; b < 8; b++) {
                    ulonglong2 h2 = *(const ulonglong2*)(h1c + b * Hn + kb + ii * 4);
                    acc[b] = fma2(w1[2 * ii],     h2.x, acc[b]);
                    acc[b] = fma2(w1[2 * ii + 1], h2.y, acc[b]);
                }
            }

            // ---- kick h0_t -> shh0[nxt] bulk copy (hidden under mvC)
            if (t < Tn && tid < 32) {
                if (tid < 16) { while (ld_acq(&f0[tid]) < (unsigned)(t + 1)) {} }
                __syncwarp();
                if (tid == 0) {
                    mbar_expect_tx(mb0, HBYTES);
                    bulk_g2s(sh0a + nxt * HBYTES, &g_h0buf[cur][group][0], HBYTES, mb0);
                }
            }

            // ---- mvC = W_ih1 . h0_{t-1}, accumulated on top of mvB
            {
                const float* wr = wih1 + j * WSTRIDE + kb;
#pragma unroll
                for (int ii = 0; ii < 8; ii++) {
                    ulonglong2 w2 = *(const ulonglong2*)(wr + ii * 4);
#pragma unroll
                    for (int b = 0; b < 8; b++) {
                        ulonglong2 h2 = *(const ulonglong2*)(h0c + b * Hn + kb + ii * 4);
                        acc[b] = fma2(w2.x, h2.x, acc[b]);
                        acc[b] = fma2(w2.y, h2.y, acc[b]);
                    }
                }
            }
#pragma unroll
            for (int b = 0; b < 8; b++) {
                float2 f = upk(acc[b]);
                part1[kg * 256 + b * 32 + j] = f.x + f.y;
            }
            __syncthreads();
            if (tid < 256) {
                float s0 = bias1, s1 = 0.f;
#pragma unroll
                for (int kk = 0; kk < 16; kk += 2) {
                    s0 += part1[kk * 256 + tid];
                    s1 += part1[(kk + 1) * 256 + tid];
                }
                float hn = tanhf(s0 + s1);
                if (t < Tn) __stcg(&g_h1buf[cur][group][rb * Hn + rcol], hn);
                else        g_hT[(group * GB + rb) * Hn + rcol] = hn;
            }
            __syncthreads();
            if (t < Tn) {
                if (tid == 0) st_rel(&f1[slice], (unsigned)t);
                // kick h1_{t-1} -> shh1[nxt] copy; consumed after next iter's mv0
                if (tid < 32) {
                    if (tid < 16) { while (ld_acq(&f1[tid]) < (unsigned)t) {} }
                    __syncwarp();
                    if (tid == 0) {
                        mbar_expect_tx(mb1, HBYTES);
                        bulk_g2s(sh1a + nxt * HBYTES, &g_h1buf[cur][group][0], HBYTES, mb1);
                    }
                }
            }
        } else {
            // t == 0: kick the very first h0 copy
            if (tid < 32) {
                if (tid < 16) { while (ld_acq(&f0[tid]) < 1u) {} }
                __syncwarp();
                if (tid == 0) {
                    mbar_expect_tx(mb0, HBYTES);
                    bulk_g2s(sh0a + HBYTES, &g_h0buf[0][group][0], HBYTES, mb0);
                }
            }
        }
    }
}

// ---------------- final FC ------------------------------------------------------
__global__ __launch_bounds__(128) void fc_kernel(
    const float* __restrict__ Wfc, const float* __restrict__ bfc,
    float* __restrict__ out)
{
    __shared__ float hs[Hn];
    const int b = blockIdx.x, tid = threadIdx.x;
    ((float4*)hs)[tid] = *(const float4*)&g_hT[b * Hn + tid * 4];
    __syncthreads();
    const float4* wr = (const float4*)(Wfc + (size_t)tid * Hn);
    float acc = 0.f;
#pragma unroll 8
    for (int i = 0; i < Hn / 4; i++) {
        float4 w = __ldg(&wr[i]);
        float4 h = ((const float4*)hs)[i];
        acc += w.x * h.x + w.y * h.y + w.z * h.z + w.w * h.w;
    }
    out[b * On + tid] = acc + bfc[tid];
}

// ---------------- launcher ------------------------------------------------------
extern "C" void kernel_launch(void* const* d_in, const int* in_sizes, int n_in,
                              void* d_out, int out_size)
{
    (void)in_sizes; (void)n_in; (void)out_size;
    const float* x     = (const float*)d_in[0];
    const float* W_ih0 = (const float*)d_in[1];
    const float* W_hh0 = (const float*)d_in[2];
    const float* b_ih0 = (const float*)d_in[3];
    const float* b_hh0 = (const float*)d_in[4];
    const float* h0_0  = (const float*)d_in[5];
    const float* W_ih1 = (const float*)d_in[6];
    const float* W_hh1 = (const float*)d_in[7];
    const float* b_ih1 = (const float*)d_in[8];
    const float* b_hh1 = (const float*)d_in[9];
    const float* h0_1  = (const float*)d_in[10];
    const float* W_fc  = (const float*)d_in[11];
    const float* b_fc  = (const float*)d_in[12];
    float* out = (float*)d_out;

    const int fused_smem =
        (SC * WSTRIDE + 4 * GB * Hn + 2 * NKG * 256) * sizeof(float);
    cudaFuncSetAttribute(fused_rnn, cudaFuncAttributeMaxDynamicSharedMemorySize, fused_smem);

    // xp0 = x @ W_ih0^T + b_ih0 + b_hh0  (block 0 also resets exchange flags)
    sgemm_xp<<<dim3((Bn * Tn) / 128, Hn / 128), 256>>>(x, W_ih0, b_ih0, b_hh0);

    // fused skewed two-layer recurrence (R3 + per-warp elected mbar waits)
    fused_rnn<<<NG * NS, NTHR, fused_smem>>>(W_hh0, W_ih1, W_hh1,
                                             b_ih1, b_hh1, h0_0, h0_1);

    // head
    fc_kernel<<<Bn, 128>>>(W_fc, b_fc, out);
}